// round 7
// baseline (speedup 1.0000x reference)
#include <cuda_runtime.h>
#include <cuda_bf16.h>
#include <cstdint>

// B = 1048576 rows, C = 64, K = 4.
// out[b] = mix0*lut(s) + mix1*clip(s0+s1+s2-2,0,1) + mix2*(s0+s1+s2>=2)
// with s = x[b,:] @ softmax(cp, axis=0).
//
// Round-7: TMA bulk-copy pipeline + PADDED smem rows (272B pitch) via one
// 256B cp.async.bulk per row. Padded pitch makes per-thread-row x reads
// conflict-free at UNIFORM f, so probs reads become warp-uniform broadcasts
// (~1 wavefront) instead of 32-address gathers (4 wavefronts). L1 wavefronts
// per tile drop ~1540 -> ~640, leaving DRAM as the only binding pipe.

#define NTHREADS    128
#define TILE_ROWS   128
#define ROW_F4      17                         // 16 data float4 + 1 pad
#define STAGE_F4    (TILE_ROWS * ROW_F4)       // 2176 float4 = 34816 B
#define ROW_BYTES   256
#define ROW_PITCH   272
#define TILE_BYTES  (TILE_ROWS * ROW_BYTES)    // 32768 payload

__device__ __forceinline__ void mbar_init(void* bar, unsigned count) {
    unsigned b = (unsigned)__cvta_generic_to_shared(bar);
    asm volatile("mbarrier.init.shared.b64 [%0], %1;" :: "r"(b), "r"(count) : "memory");
}
__device__ __forceinline__ void mbar_expect_tx(void* bar, unsigned bytes) {
    unsigned b = (unsigned)__cvta_generic_to_shared(bar);
    asm volatile("mbarrier.arrive.expect_tx.shared.b64 _, [%0], %1;"
                 :: "r"(b), "r"(bytes) : "memory");
}
__device__ __forceinline__ void mbar_wait_acq(void* bar, unsigned parity) {
    unsigned b = (unsigned)__cvta_generic_to_shared(bar);
    asm volatile(
        "{\n\t"
        ".reg .pred P;\n\t"
        "WAIT_%=:\n\t"
        "mbarrier.try_wait.parity.acquire.cta.shared::cta.b64 P, [%0], %1;\n\t"
        "@!P bra WAIT_%=;\n\t"
        "}"
        :: "r"(b), "r"(parity) : "memory");
}
__device__ __forceinline__ void fence_proxy_async_cta() {
    asm volatile("fence.proxy.async.shared::cta;" ::: "memory");
}
__device__ __forceinline__ void cp_bulk(void* smem_dst, const void* gsrc,
                                        unsigned bytes, void* bar) {
    unsigned s = (unsigned)__cvta_generic_to_shared(smem_dst);
    unsigned b = (unsigned)__cvta_generic_to_shared(bar);
    asm volatile(
        "cp.async.bulk.shared::cta.global.mbarrier::complete_tx::bytes "
        "[%0], [%1], %2, [%3];"
        :: "r"(s), "l"(gsrc), "r"(bytes), "r"(b) : "memory");
}

extern __shared__ float4 g_smem[];
// layout: [2*STAGE_F4] padded x tiles | [64] probs (c-major float4) | 24 floats

__global__ void __launch_bounds__(NTHREADS)
lab_fused_kernel(const float* __restrict__ x,
                 const float* __restrict__ cp,    // [64,4]
                 const float* __restrict__ lut,   // 16
                 const float* __restrict__ mix,   // 3
                 float* __restrict__ out,
                 int ntiles)
{
    float4* s_x     = g_smem;                    // 2 padded stages
    float4* s_probs = g_smem + 2 * STAGE_F4;     // probs[c] = {p_c0..p_c3}
    float*  s_tail  = reinterpret_cast<float*>(s_probs + 64);
    float*  s_lut   = s_tail;        // 16
    float*  s_mix   = s_tail + 16;   // 3
    float*  s_inv   = s_tail + 20;   // 4
    float*  s_probs_f = reinterpret_cast<float*>(s_probs);

    __shared__ __align__(8) uint64_t s_bar[2];

    const int tid = threadIdx.x;

    // ---- per-block parameter prep (once; layout identical to round 2) ----
    s_probs_f[tid]       = __expf(cp[tid]);
    s_probs_f[tid + 128] = __expf(cp[tid + 128]);
    if (tid < 16) s_lut[tid] = 1.0f / (1.0f + __expf(-lut[tid]));
    if (tid == 32) {
        float m0 = __expf(mix[0]), m1 = __expf(mix[1]), m2 = __expf(mix[2]);
        float inv = 1.0f / (m0 + m1 + m2);
        s_mix[0] = m0 * inv; s_mix[1] = m1 * inv; s_mix[2] = m2 * inv;
    }
    if (tid == 0) {
        mbar_init(&s_bar[0], 4);                 // 4 producer threads arrive
        mbar_init(&s_bar[1], 4);
    }
    __syncthreads();
    if (tid == 0) fence_proxy_async_cta();       // order mbar init before TMA use
    __syncthreads();

    if (tid < 32) {                              // column sums: lane t sums k = t%4
        float acc = 0.0f;
        #pragma unroll
        for (int i = 0; i < 8; ++i) acc += s_probs_f[tid + 32 * i];
        #pragma unroll
        for (int off = 16; off >= 4; off >>= 1)
            acc += __shfl_down_sync(0xffffffffu, acc, off);
        if (tid < 4) s_inv[tid] = 1.0f / acc;
    }
    __syncthreads();

    s_probs_f[tid]       *= s_inv[tid & 3];      // normalize in place
    s_probs_f[tid + 128] *= s_inv[tid & 3];
    __syncthreads();

    const char* __restrict__ xb = reinterpret_cast<const char*>(x);
    const int stride = gridDim.x;
    const bool producer = ((tid & 31) == 0);     // lane 0 of each warp
    const int  pwarp    = tid >> 5;              // producer's row group

    // producer: 32 per-row 256B bulk copies into padded stage
    auto load_tile = [&](int tile, int stage) {
        fence_proxy_async_cta();                 // prior LDS reads -> TMA writes
        mbar_expect_tx(&s_bar[stage], TILE_BYTES / 4);
        const char* src = xb + (size_t)tile * TILE_BYTES + pwarp * 32 * ROW_BYTES;
        char* dst = reinterpret_cast<char*>(s_x + stage * STAGE_F4)
                  + pwarp * 32 * ROW_PITCH;
        #pragma unroll
        for (int r = 0; r < 32; ++r)
            cp_bulk(dst + r * ROW_PITCH, src + r * ROW_BYTES, ROW_BYTES,
                    &s_bar[stage]);
    };

    // ---- software pipeline: double-buffered padded tiles ----
    int tile = blockIdx.x;
    if (producer && tile < ntiles) load_tile(tile, 0);

    int buf = 0;
    unsigned ph0 = 0, ph1 = 0;                   // per-stage phase parity
    for (; tile < ntiles; tile += stride) {
        const int nxt = tile + stride;
        if (producer && nxt < ntiles) load_tile(nxt, buf ^ 1);

        // wait (acquire) for current buffer: TMA writes visible to LDS
        if (buf == 0) { mbar_wait_acq(&s_bar[0], ph0); ph0 ^= 1; }
        else          { mbar_wait_acq(&s_bar[1], ph1); ph1 ^= 1; }

        const float4* __restrict__ xr = s_x + buf * STAGE_F4 + tid * ROW_F4;
        float a0 = 0.0f, a1 = 0.0f, a2 = 0.0f, a3 = 0.0f;
        #pragma unroll
        for (int f = 0; f < 16; ++f) {
            const float4 xv = xr[f];                  // padded: conflict-free
            const float4 p0 = s_probs[4 * f + 0];     // warp-uniform broadcast
            const float4 p1 = s_probs[4 * f + 1];
            const float4 p2 = s_probs[4 * f + 2];
            const float4 p3 = s_probs[4 * f + 3];
            a0 = fmaf(xv.x, p0.x, a0); a1 = fmaf(xv.x, p0.y, a1);
            a2 = fmaf(xv.x, p0.z, a2); a3 = fmaf(xv.x, p0.w, a3);
            a0 = fmaf(xv.y, p1.x, a0); a1 = fmaf(xv.y, p1.y, a1);
            a2 = fmaf(xv.y, p1.z, a2); a3 = fmaf(xv.y, p1.w, a3);
            a0 = fmaf(xv.z, p2.x, a0); a1 = fmaf(xv.z, p2.y, a1);
            a2 = fmaf(xv.z, p2.z, a2); a3 = fmaf(xv.z, p2.w, a3);
            a0 = fmaf(xv.w, p3.x, a0); a1 = fmaf(xv.w, p3.y, a1);
            a2 = fmaf(xv.w, p3.z, a2); a3 = fmaf(xv.w, p3.w, a3);
        }

        const float s0 = a0, s1 = a1, s2 = a2, s3 = a3;

        // addition path
        const float add = s0 + s1 + s2;
        const float ao1 = fminf(fmaxf(add - 2.0f, 0.0f), 1.0f);
        const float ao2 = (add >= 2.0f) ? 1.0f : 0.0f;

        // multilinear contraction over sigmoid(lut)[2,2,2,2]; bit0 -> s, bit1 -> 1-s
        const float w3b = 1.0f - s3;
        const float u0 = s_lut[ 0] * s3 + s_lut[ 1] * w3b;
        const float u1 = s_lut[ 2] * s3 + s_lut[ 3] * w3b;
        const float u2 = s_lut[ 4] * s3 + s_lut[ 5] * w3b;
        const float u3 = s_lut[ 6] * s3 + s_lut[ 7] * w3b;
        const float u4 = s_lut[ 8] * s3 + s_lut[ 9] * w3b;
        const float u5 = s_lut[10] * s3 + s_lut[11] * w3b;
        const float u6 = s_lut[12] * s3 + s_lut[13] * w3b;
        const float u7 = s_lut[14] * s3 + s_lut[15] * w3b;

        const float w2b = 1.0f - s2;
        const float v0 = u0 * s2 + u1 * w2b;
        const float v1 = u2 * s2 + u3 * w2b;
        const float v2 = u4 * s2 + u5 * w2b;
        const float v3 = u6 * s2 + u7 * w2b;

        const float w1b = 1.0f - s1;
        const float r0 = v0 * s1 + v1 * w1b;
        const float r1 = v2 * s1 + v3 * w1b;

        const float lut_out = r0 * s0 + r1 * (1.0f - s0);

        out[tile * TILE_ROWS + tid] = s_mix[0] * lut_out + s_mix[1] * ao1 + s_mix[2] * ao2;

        __syncthreads();   // all reads of buf done before it is refilled
        buf ^= 1;
    }
}

extern "C" void kernel_launch(void* const* d_in, const int* in_sizes, int n_in,
                              void* d_out, int out_size)
{
    const float* x   = (const float*)d_in[0];   // [B, 64]
    const float* cp  = (const float*)d_in[1];   // [64, 4]
    const float* lut = (const float*)d_in[2];   // 16
    const float* mix = (const float*)d_in[3];   // 3
    float* out = (float*)d_out;

    const int B      = in_sizes[0] / 64;
    const int ntiles = B / TILE_ROWS;           // 8192

    const int smem_bytes = (2 * STAGE_F4 + 64) * sizeof(float4) + 24 * sizeof(float);

    static bool attr_set = false;               // idempotent, host-side only
    if (!attr_set) {
        cudaFuncSetAttribute(lab_fused_kernel,
                             cudaFuncAttributeMaxDynamicSharedMemorySize, smem_bytes);
        attr_set = true;
    }

    int grid = 444;                             // 3 CTAs/SM x 148 SMs, one wave
    if (grid > ntiles) grid = ntiles;

    lab_fused_kernel<<<grid, NTHREADS, smem_bytes>>>(x, cp, lut, mix, out, ntiles);
}

// round 9
// speedup vs baseline: 1.2560x; 1.2560x over previous
#include <cuda_runtime.h>
#include <cuda.h>
#include <cuda_bf16.h>
#include <cstdint>
#include <dlfcn.h>

// B = 1048576 rows, C = 64, K = 4.
// out[b] = mix0*lut(s) + mix1*clip(s0+s1+s2-2,0,1) + mix2*(s0+s1+s2>=2)
// with s = x[b,:] @ softmax(cp, axis=0).
//
// Round-9: round-8 TMA SW128 tensor-map design + the missing 1024B smem
// alignment for swizzled TMA destinations (dynamic smem base is NOT
// atom-aligned once static smem exists; align manually, +1KB slack).

#define NTHREADS    128
#define TILE_ROWS   128
#define STAGE_F4    (TILE_ROWS * 16)          // 2048 float4 = 32 KB (L+R halves)
#define HALF_F4     (STAGE_F4 / 2)            // 1024 float4 = 16 KB
#define TILE_BYTES  (TILE_ROWS * 256)         // 32768

__device__ __forceinline__ void mbar_init(void* bar, unsigned count) {
    unsigned b = (unsigned)__cvta_generic_to_shared(bar);
    asm volatile("mbarrier.init.shared.b64 [%0], %1;" :: "r"(b), "r"(count) : "memory");
}
__device__ __forceinline__ void mbar_expect_tx(void* bar, unsigned bytes) {
    unsigned b = (unsigned)__cvta_generic_to_shared(bar);
    asm volatile("mbarrier.arrive.expect_tx.shared.b64 _, [%0], %1;"
                 :: "r"(b), "r"(bytes) : "memory");
}
__device__ __forceinline__ void mbar_wait_acq(void* bar, unsigned parity) {
    unsigned b = (unsigned)__cvta_generic_to_shared(bar);
    asm volatile(
        "{\n\t"
        ".reg .pred P;\n\t"
        "WAIT_%=:\n\t"
        "mbarrier.try_wait.parity.acquire.cta.shared::cta.b64 P, [%0], %1;\n\t"
        "@!P bra WAIT_%=;\n\t"
        "}"
        :: "r"(b), "r"(parity) : "memory");
}
__device__ __forceinline__ void fence_proxy_async_cta() {
    asm volatile("fence.proxy.async.shared::cta;" ::: "memory");
}
__device__ __forceinline__ void tma_load_2d(uint32_t smem_dst, const void* tmap,
                                            int cx, int cy, void* bar) {
    unsigned b = (unsigned)__cvta_generic_to_shared(bar);
    asm volatile(
        "cp.async.bulk.tensor.2d.shared::cta.global.tile.mbarrier::complete_tx::bytes "
        "[%0], [%1, {%2, %3}], [%4];"
        :: "r"(smem_dst), "l"(tmap), "r"(cx), "r"(cy), "r"(b) : "memory");
}

extern __shared__ char g_smem_raw[];
// after 1024B alignment: [2*STAGE_F4] swizzled x tiles | [64] probs f4 | 24 floats

__global__ void __launch_bounds__(NTHREADS)
lab_fused_kernel(const __grid_constant__ CUtensorMap tmapL,
                 const __grid_constant__ CUtensorMap tmapR,
                 const float* __restrict__ cp,    // [64,4]
                 const float* __restrict__ lut,   // 16
                 const float* __restrict__ mix,   // 3
                 float* __restrict__ out,
                 int ntiles)
{
    // align tile base to the 1024B SW128 swizzle atom
    const uint32_t raw_s   = (uint32_t)__cvta_generic_to_shared(g_smem_raw);
    const uint32_t align_off = ((raw_s + 1023u) & ~1023u) - raw_s;
    char* base = g_smem_raw + align_off;

    float4* s_x     = reinterpret_cast<float4*>(base);      // 2 stages
    float4* s_probs = s_x + 2 * STAGE_F4;                   // probs[c]={p_c0..p_c3}
    float*  s_tail  = reinterpret_cast<float*>(s_probs + 64);
    float*  s_lut   = s_tail;        // 16
    float*  s_mix   = s_tail + 16;   // 3
    float*  s_inv   = s_tail + 20;   // 4
    float*  s_probs_f = reinterpret_cast<float*>(s_probs);

    __shared__ __align__(8) uint64_t s_bar[2];

    const int tid = threadIdx.x;

    // ---- per-block parameter prep (once) ----
    s_probs_f[tid]       = __expf(cp[tid]);
    s_probs_f[tid + 128] = __expf(cp[tid + 128]);
    if (tid < 16) s_lut[tid] = 1.0f / (1.0f + __expf(-lut[tid]));
    if (tid == 32) {
        float m0 = __expf(mix[0]), m1 = __expf(mix[1]), m2 = __expf(mix[2]);
        float inv = 1.0f / (m0 + m1 + m2);
        s_mix[0] = m0 * inv; s_mix[1] = m1 * inv; s_mix[2] = m2 * inv;
    }
    if (tid == 0) {
        mbar_init(&s_bar[0], 1);
        mbar_init(&s_bar[1], 1);
    }
    __syncthreads();
    if (tid == 0) fence_proxy_async_cta();       // order mbar init before TMA use
    __syncthreads();

    if (tid < 32) {                              // column sums: lane t sums k = t%4
        float acc = 0.0f;
        #pragma unroll
        for (int i = 0; i < 8; ++i) acc += s_probs_f[tid + 32 * i];
        #pragma unroll
        for (int off = 16; off >= 4; off >>= 1)
            acc += __shfl_down_sync(0xffffffffu, acc, off);
        if (tid < 4) s_inv[tid] = 1.0f / acc;
    }
    __syncthreads();

    s_probs_f[tid]       *= s_inv[tid & 3];      // normalize in place
    s_probs_f[tid + 128] *= s_inv[tid & 3];
    __syncthreads();

    const int stride = gridDim.x;
    const uint32_t smem_x0 = raw_s + align_off;  // 1024B-aligned

    // one tile = two 16KB swizzled tensor loads (left/right half-rows)
    auto load_tile = [&](int tile, int stage) {
        fence_proxy_async_cta();                 // prior LDS reads -> TMA writes
        mbar_expect_tx(&s_bar[stage], TILE_BYTES);
        uint32_t dst = smem_x0 + stage * (STAGE_F4 * 16);
        tma_load_2d(dst,                &tmapL, 0, tile * TILE_ROWS, &s_bar[stage]);
        tma_load_2d(dst + HALF_F4 * 16, &tmapR, 0, tile * TILE_ROWS, &s_bar[stage]);
    };

    // ---- software pipeline: double-buffered swizzled tiles ----
    int tile = blockIdx.x;
    if (tid == 0 && tile < ntiles) load_tile(tile, 0);

    const int r7 = tid & 7;                      // swizzle phase of this row

    int buf = 0;
    unsigned ph0 = 0, ph1 = 0;                   // per-stage phase parity
    for (; tile < ntiles; tile += stride) {
        const int nxt = tile + stride;
        if (tid == 0 && nxt < ntiles) load_tile(nxt, buf ^ 1);

        // wait (acquire) for current buffer: TMA writes visible to LDS
        if (buf == 0) { mbar_wait_acq(&s_bar[0], ph0); ph0 ^= 1; }
        else          { mbar_wait_acq(&s_bar[1], ph1); ph1 ^= 1; }

        // row r at 128B pitch in each half; chunk f at index (f ^ r7)
        const float4* __restrict__ xl = s_x + buf * STAGE_F4 + tid * 8;   // f 0..7
        const float4* __restrict__ xh = xl + HALF_F4;                      // f 8..15
        float a0 = 0.0f, a1 = 0.0f, a2 = 0.0f, a3 = 0.0f;
        #pragma unroll
        for (int f = 0; f < 16; ++f) {
            const float4 xv = (f < 8) ? xl[f ^ r7] : xh[(f - 8) ^ r7];
            const float4 p0 = s_probs[4 * f + 0];     // warp-uniform broadcast
            const float4 p1 = s_probs[4 * f + 1];
            const float4 p2 = s_probs[4 * f + 2];
            const float4 p3 = s_probs[4 * f + 3];
            a0 = fmaf(xv.x, p0.x, a0); a1 = fmaf(xv.x, p0.y, a1);
            a2 = fmaf(xv.x, p0.z, a2); a3 = fmaf(xv.x, p0.w, a3);
            a0 = fmaf(xv.y, p1.x, a0); a1 = fmaf(xv.y, p1.y, a1);
            a2 = fmaf(xv.y, p1.z, a2); a3 = fmaf(xv.y, p1.w, a3);
            a0 = fmaf(xv.z, p2.x, a0); a1 = fmaf(xv.z, p2.y, a1);
            a2 = fmaf(xv.z, p2.z, a2); a3 = fmaf(xv.z, p2.w, a3);
            a0 = fmaf(xv.w, p3.x, a0); a1 = fmaf(xv.w, p3.y, a1);
            a2 = fmaf(xv.w, p3.z, a2); a3 = fmaf(xv.w, p3.w, a3);
        }

        const float s0 = a0, s1 = a1, s2 = a2, s3 = a3;

        // addition path
        const float add = s0 + s1 + s2;
        const float ao1 = fminf(fmaxf(add - 2.0f, 0.0f), 1.0f);
        const float ao2 = (add >= 2.0f) ? 1.0f : 0.0f;

        // multilinear contraction over sigmoid(lut)[2,2,2,2]; bit0 -> s, bit1 -> 1-s
        const float w3b = 1.0f - s3;
        const float u0 = s_lut[ 0] * s3 + s_lut[ 1] * w3b;
        const float u1 = s_lut[ 2] * s3 + s_lut[ 3] * w3b;
        const float u2 = s_lut[ 4] * s3 + s_lut[ 5] * w3b;
        const float u3 = s_lut[ 6] * s3 + s_lut[ 7] * w3b;
        const float u4 = s_lut[ 8] * s3 + s_lut[ 9] * w3b;
        const float u5 = s_lut[10] * s3 + s_lut[11] * w3b;
        const float u6 = s_lut[12] * s3 + s_lut[13] * w3b;
        const float u7 = s_lut[14] * s3 + s_lut[15] * w3b;

        const float w2b = 1.0f - s2;
        const float v0 = u0 * s2 + u1 * w2b;
        const float v1 = u2 * s2 + u3 * w2b;
        const float v2 = u4 * s2 + u5 * w2b;
        const float v3 = u6 * s2 + u7 * w2b;

        const float w1b = 1.0f - s1;
        const float r0 = v0 * s1 + v1 * w1b;
        const float r1 = v2 * s1 + v3 * w1b;

        const float lut_out = r0 * s0 + r1 * (1.0f - s0);

        out[tile * TILE_ROWS + tid] = s_mix[0] * lut_out + s_mix[1] * ao1 + s_mix[2] * ao2;

        __syncthreads();   // all reads of buf done before it is refilled
        buf ^= 1;
    }
}

extern "C" void kernel_launch(void* const* d_in, const int* in_sizes, int n_in,
                              void* d_out, int out_size)
{
    const float* x   = (const float*)d_in[0];   // [B, 64]
    const float* cp  = (const float*)d_in[1];   // [64, 4]
    const float* lut = (const float*)d_in[2];   // 16
    const float* mix = (const float*)d_in[3];   // 3
    float* out = (float*)d_out;

    const int B      = in_sizes[0] / 64;
    const int ntiles = B / TILE_ROWS;           // 8192

    // resolve cuTensorMapEncodeTiled without a -lcuda link dependency
    typedef CUresult (*EncodeFn)(CUtensorMap*, CUtensorMapDataType, cuuint32_t,
                                 void*, const cuuint64_t*, const cuuint64_t*,
                                 const cuuint32_t*, const cuuint32_t*,
                                 CUtensorMapInterleave, CUtensorMapSwizzle,
                                 CUtensorMapL2promotion, CUtensorMapFloatOOBfill);
    static EncodeFn enc = nullptr;              // host-side cache, deterministic
    if (!enc) {
        void* h = dlopen("libcuda.so.1", RTLD_NOW | RTLD_GLOBAL);
        if (!h) h = dlopen("libcuda.so", RTLD_NOW | RTLD_GLOBAL);
        enc = (EncodeFn)dlsym(h, "cuTensorMapEncodeTiled");
    }

    // two half-row descriptors: 32-float inner dim (128B = SW128 atom width),
    // row stride 256B; R half starts 128B into each row.
    cuuint64_t gdim[2]    = {32, (cuuint64_t)B};
    cuuint64_t gstride[1] = {256};
    cuuint32_t box[2]     = {32, TILE_ROWS};
    cuuint32_t estr[2]    = {1, 1};

    CUtensorMap tL, tR;
    enc(&tL, CU_TENSOR_MAP_DATA_TYPE_FLOAT32, 2, (void*)x,
        gdim, gstride, box, estr,
        CU_TENSOR_MAP_INTERLEAVE_NONE, CU_TENSOR_MAP_SWIZZLE_128B,
        CU_TENSOR_MAP_L2_PROMOTION_L2_128B, CU_TENSOR_MAP_FLOAT_OOB_FILL_NONE);
    enc(&tR, CU_TENSOR_MAP_DATA_TYPE_FLOAT32, 2, (void*)((const char*)x + 128),
        gdim, gstride, box, estr,
        CU_TENSOR_MAP_INTERLEAVE_NONE, CU_TENSOR_MAP_SWIZZLE_128B,
        CU_TENSOR_MAP_L2_PROMOTION_L2_128B, CU_TENSOR_MAP_FLOAT_OOB_FILL_NONE);

    // +1KB slack so the kernel can align the tile base to the swizzle atom
    const int smem_bytes = 1024 + (2 * STAGE_F4 + 64) * sizeof(float4)
                         + 24 * sizeof(float);

    static bool attr_set = false;               // idempotent, host-side only
    if (!attr_set) {
        cudaFuncSetAttribute(lab_fused_kernel,
                             cudaFuncAttributeMaxDynamicSharedMemorySize, smem_bytes);
        attr_set = true;
    }

    int grid = 444;                             // 3 CTAs/SM x 148 SMs, one wave
    if (grid > ntiles) grid = ntiles;

    lab_fused_kernel<<<grid, NTHREADS, smem_bytes>>>(tL, tR, cp, lut, mix, out, ntiles);
}

// round 10
// speedup vs baseline: 1.2671x; 1.0088x over previous
#include <cuda_runtime.h>
#include <cuda.h>
#include <cuda_bf16.h>
#include <cstdint>
#include <dlfcn.h>

// B = 1048576 rows, C = 64, K = 4.
// out[b] = mix0*lut(s) + mix1*clip(s0+s1+s2-2,0,1) + mix2*(s0+s1+s2>=2)
// with s = x[b,:] @ softmax(cp, axis=0).
//
// Round-10: SW128 tensor-map TMA pipeline deepened to a 3-stage ring
// (prefetch distance 2), 2 CTAs/SM. Removes the prefetch-distance-1 duty
// cycle cap that held DRAM at ~77%.

#define NTHREADS    128
#define TILE_ROWS   128
#define STAGE_F4    (TILE_ROWS * 16)          // 2048 float4 = 32 KB (L+R halves)
#define HALF_F4     (STAGE_F4 / 2)            // 1024 float4 = 16 KB
#define TILE_BYTES  (TILE_ROWS * 256)         // 32768
#define NSTAGES     3

__device__ __forceinline__ void mbar_init(void* bar, unsigned count) {
    unsigned b = (unsigned)__cvta_generic_to_shared(bar);
    asm volatile("mbarrier.init.shared.b64 [%0], %1;" :: "r"(b), "r"(count) : "memory");
}
__device__ __forceinline__ void mbar_expect_tx(void* bar, unsigned bytes) {
    unsigned b = (unsigned)__cvta_generic_to_shared(bar);
    asm volatile("mbarrier.arrive.expect_tx.shared.b64 _, [%0], %1;"
                 :: "r"(b), "r"(bytes) : "memory");
}
__device__ __forceinline__ void mbar_wait_acq(void* bar, unsigned parity) {
    unsigned b = (unsigned)__cvta_generic_to_shared(bar);
    asm volatile(
        "{\n\t"
        ".reg .pred P;\n\t"
        "WAIT_%=:\n\t"
        "mbarrier.try_wait.parity.acquire.cta.shared::cta.b64 P, [%0], %1;\n\t"
        "@!P bra WAIT_%=;\n\t"
        "}"
        :: "r"(b), "r"(parity) : "memory");
}
__device__ __forceinline__ void fence_proxy_async_cta() {
    asm volatile("fence.proxy.async.shared::cta;" ::: "memory");
}
__device__ __forceinline__ void tma_load_2d(uint32_t smem_dst, const void* tmap,
                                            int cx, int cy, void* bar) {
    unsigned b = (unsigned)__cvta_generic_to_shared(bar);
    asm volatile(
        "cp.async.bulk.tensor.2d.shared::cta.global.tile.mbarrier::complete_tx::bytes "
        "[%0], [%1, {%2, %3}], [%4];"
        :: "r"(smem_dst), "l"(tmap), "r"(cx), "r"(cy), "r"(b) : "memory");
}

extern __shared__ char g_smem_raw[];
// after 1024B alignment: [NSTAGES*STAGE_F4] swizzled x | [64] probs f4 | 24 floats

__global__ void __launch_bounds__(NTHREADS)
lab_fused_kernel(const __grid_constant__ CUtensorMap tmapL,
                 const __grid_constant__ CUtensorMap tmapR,
                 const float* __restrict__ cp,    // [64,4]
                 const float* __restrict__ lut,   // 16
                 const float* __restrict__ mix,   // 3
                 float* __restrict__ out,
                 int ntiles)
{
    // align tile base to the 1024B SW128 swizzle atom
    const uint32_t raw_s     = (uint32_t)__cvta_generic_to_shared(g_smem_raw);
    const uint32_t align_off = ((raw_s + 1023u) & ~1023u) - raw_s;
    char* base = g_smem_raw + align_off;

    float4* s_x     = reinterpret_cast<float4*>(base);          // NSTAGES stages
    float4* s_probs = s_x + NSTAGES * STAGE_F4;                 // probs[c]
    float*  s_tail  = reinterpret_cast<float*>(s_probs + 64);
    float*  s_lut   = s_tail;        // 16
    float*  s_mix   = s_tail + 16;   // 3
    float*  s_inv   = s_tail + 20;   // 4
    float*  s_probs_f = reinterpret_cast<float*>(s_probs);

    __shared__ __align__(8) uint64_t s_bar[NSTAGES];

    const int tid = threadIdx.x;

    // ---- per-block parameter prep (once) ----
    s_probs_f[tid]       = __expf(cp[tid]);
    s_probs_f[tid + 128] = __expf(cp[tid + 128]);
    if (tid < 16) s_lut[tid] = 1.0f / (1.0f + __expf(-lut[tid]));
    if (tid == 32) {
        float m0 = __expf(mix[0]), m1 = __expf(mix[1]), m2 = __expf(mix[2]);
        float inv = 1.0f / (m0 + m1 + m2);
        s_mix[0] = m0 * inv; s_mix[1] = m1 * inv; s_mix[2] = m2 * inv;
    }
    if (tid == 0) {
        #pragma unroll
        for (int i = 0; i < NSTAGES; ++i) mbar_init(&s_bar[i], 1);
    }
    __syncthreads();
    if (tid == 0) fence_proxy_async_cta();       // order mbar init before TMA use
    __syncthreads();

    if (tid < 32) {                              // column sums: lane t sums k = t%4
        float acc = 0.0f;
        #pragma unroll
        for (int i = 0; i < 8; ++i) acc += s_probs_f[tid + 32 * i];
        #pragma unroll
        for (int off = 16; off >= 4; off >>= 1)
            acc += __shfl_down_sync(0xffffffffu, acc, off);
        if (tid < 4) s_inv[tid] = 1.0f / acc;
    }
    __syncthreads();

    s_probs_f[tid]       *= s_inv[tid & 3];      // normalize in place
    s_probs_f[tid + 128] *= s_inv[tid & 3];
    __syncthreads();

    const int stride = gridDim.x;
    const uint32_t smem_x0 = raw_s + align_off;  // 1024B-aligned

    // one tile = two 16KB swizzled tensor loads (left/right half-rows)
    auto load_tile = [&](int tile, int stage) {
        fence_proxy_async_cta();                 // prior LDS reads -> TMA writes
        mbar_expect_tx(&s_bar[stage], TILE_BYTES);
        uint32_t dst = smem_x0 + stage * (STAGE_F4 * 16);
        tma_load_2d(dst,                &tmapL, 0, tile * TILE_ROWS, &s_bar[stage]);
        tma_load_2d(dst + HALF_F4 * 16, &tmapR, 0, tile * TILE_ROWS, &s_bar[stage]);
    };

    // ---- 3-stage software pipeline: prefetch distance 2 ----
    int tile = blockIdx.x;
    if (tid == 0) {
        if (tile < ntiles)               load_tile(tile, 0);
        if (tile + stride < ntiles)      load_tile(tile + stride, 1);
    }

    const int r7 = tid & 7;                      // swizzle phase of this row

    int s = 0;                                   // current stage
    unsigned ph = 0;                             // per-stage parity bits
    for (; tile < ntiles; tile += stride) {
        // wait (acquire) for current stage: TMA writes visible to LDS
        mbar_wait_acq(&s_bar[s], (ph >> s) & 1u);
        ph ^= (1u << s);

        // row r at 128B pitch in each half; chunk f at index (f ^ r7)
        const float4* __restrict__ xl = s_x + s * STAGE_F4 + tid * 8;   // f 0..7
        const float4* __restrict__ xh = xl + HALF_F4;                   // f 8..15
        float a0 = 0.0f, a1 = 0.0f, a2 = 0.0f, a3 = 0.0f;
        #pragma unroll
        for (int f = 0; f < 16; ++f) {
            const float4 xv = (f < 8) ? xl[f ^ r7] : xh[(f - 8) ^ r7];
            const float4 p0 = s_probs[4 * f + 0];     // warp-uniform broadcast
            const float4 p1 = s_probs[4 * f + 1];
            const float4 p2 = s_probs[4 * f + 2];
            const float4 p3 = s_probs[4 * f + 3];
            a0 = fmaf(xv.x, p0.x, a0); a1 = fmaf(xv.x, p0.y, a1);
            a2 = fmaf(xv.x, p0.z, a2); a3 = fmaf(xv.x, p0.w, a3);
            a0 = fmaf(xv.y, p1.x, a0); a1 = fmaf(xv.y, p1.y, a1);
            a2 = fmaf(xv.y, p1.z, a2); a3 = fmaf(xv.y, p1.w, a3);
            a0 = fmaf(xv.z, p2.x, a0); a1 = fmaf(xv.z, p2.y, a1);
            a2 = fmaf(xv.z, p2.z, a2); a3 = fmaf(xv.z, p2.w, a3);
            a0 = fmaf(xv.w, p3.x, a0); a1 = fmaf(xv.w, p3.y, a1);
            a2 = fmaf(xv.w, p3.z, a2); a3 = fmaf(xv.w, p3.w, a3);
        }

        const float s0 = a0, s1 = a1, s2 = a2, s3 = a3;

        // addition path
        const float add = s0 + s1 + s2;
        const float ao1 = fminf(fmaxf(add - 2.0f, 0.0f), 1.0f);
        const float ao2 = (add >= 2.0f) ? 1.0f : 0.0f;

        // multilinear contraction over sigmoid(lut)[2,2,2,2]; bit0 -> s, bit1 -> 1-s
        const float w3b = 1.0f - s3;
        const float u0 = s_lut[ 0] * s3 + s_lut[ 1] * w3b;
        const float u1 = s_lut[ 2] * s3 + s_lut[ 3] * w3b;
        const float u2 = s_lut[ 4] * s3 + s_lut[ 5] * w3b;
        const float u3 = s_lut[ 6] * s3 + s_lut[ 7] * w3b;
        const float u4 = s_lut[ 8] * s3 + s_lut[ 9] * w3b;
        const float u5 = s_lut[10] * s3 + s_lut[11] * w3b;
        const float u6 = s_lut[12] * s3 + s_lut[13] * w3b;
        const float u7 = s_lut[14] * s3 + s_lut[15] * w3b;

        const float w2b = 1.0f - s2;
        const float v0 = u0 * s2 + u1 * w2b;
        const float v1 = u2 * s2 + u3 * w2b;
        const float v2 = u4 * s2 + u5 * w2b;
        const float v3 = u6 * s2 + u7 * w2b;

        const float w1b = 1.0f - s1;
        const float r0 = v0 * s1 + v1 * w1b;
        const float r1 = v2 * s1 + v3 * w1b;

        const float lut_out = r0 * s0 + r1 * (1.0f - s0);

        out[tile * TILE_ROWS + tid] = s_mix[0] * lut_out + s_mix[1] * ao1 + s_mix[2] * ao2;

        __syncthreads();   // all reads of stage s done before it is refilled

        // prefetch tile t+2*stride into this (just-freed) ring slot's successor
        const int pre = tile + 2 * stride;
        if (tid == 0 && pre < ntiles) {
            int sp = s + 2; if (sp >= NSTAGES) sp -= NSTAGES;
            load_tile(pre, sp);
        }

        if (++s == NSTAGES) s = 0;
    }
}

extern "C" void kernel_launch(void* const* d_in, const int* in_sizes, int n_in,
                              void* d_out, int out_size)
{
    const float* x   = (const float*)d_in[0];   // [B, 64]
    const float* cp  = (const float*)d_in[1];   // [64, 4]
    const float* lut = (const float*)d_in[2];   // 16
    const float* mix = (const float*)d_in[3];   // 3
    float* out = (float*)d_out;

    const int B      = in_sizes[0] / 64;
    const int ntiles = B / TILE_ROWS;           // 8192

    // resolve cuTensorMapEncodeTiled without a -lcuda link dependency
    typedef CUresult (*EncodeFn)(CUtensorMap*, CUtensorMapDataType, cuuint32_t,
                                 void*, const cuuint64_t*, const cuuint64_t*,
                                 const cuuint32_t*, const cuuint32_t*,
                                 CUtensorMapInterleave, CUtensorMapSwizzle,
                                 CUtensorMapL2promotion, CUtensorMapFloatOOBfill);
    static EncodeFn enc = nullptr;              // host-side cache, deterministic
    if (!enc) {
        void* h = dlopen("libcuda.so.1", RTLD_NOW | RTLD_GLOBAL);
        if (!h) h = dlopen("libcuda.so", RTLD_NOW | RTLD_GLOBAL);
        enc = (EncodeFn)dlsym(h, "cuTensorMapEncodeTiled");
    }

    // two half-row descriptors: 32-float inner dim (128B = SW128 atom width),
    // row stride 256B; R half starts 128B into each row.
    cuuint64_t gdim[2]    = {32, (cuuint64_t)B};
    cuuint64_t gstride[1] = {256};
    cuuint32_t box[2]     = {32, TILE_ROWS};
    cuuint32_t estr[2]    = {1, 1};

    CUtensorMap tL, tR;
    enc(&tL, CU_TENSOR_MAP_DATA_TYPE_FLOAT32, 2, (void*)x,
        gdim, gstride, box, estr,
        CU_TENSOR_MAP_INTERLEAVE_NONE, CU_TENSOR_MAP_SWIZZLE_128B,
        CU_TENSOR_MAP_L2_PROMOTION_L2_128B, CU_TENSOR_MAP_FLOAT_OOB_FILL_NONE);
    enc(&tR, CU_TENSOR_MAP_DATA_TYPE_FLOAT32, 2, (void*)((const char*)x + 128),
        gdim, gstride, box, estr,
        CU_TENSOR_MAP_INTERLEAVE_NONE, CU_TENSOR_MAP_SWIZZLE_128B,
        CU_TENSOR_MAP_L2_PROMOTION_L2_128B, CU_TENSOR_MAP_FLOAT_OOB_FILL_NONE);

    // +1KB alignment slack; 3 stages of 32KB; probs + tail
    const int smem_bytes = 1024 + (NSTAGES * STAGE_F4 + 64) * sizeof(float4)
                         + 24 * sizeof(float);

    static bool attr_set = false;               // idempotent, host-side only
    if (!attr_set) {
        cudaFuncSetAttribute(lab_fused_kernel,
                             cudaFuncAttributeMaxDynamicSharedMemorySize, smem_bytes);
        attr_set = true;
    }

    int grid = 296;                             // 2 CTAs/SM x 148 SMs, one wave
    if (grid > ntiles) grid = ntiles;

    lab_fused_kernel<<<grid, NTHREADS, smem_bytes>>>(tL, tR, cp, lut, mix, out, ntiles);
}